// round 5
// baseline (speedup 1.0000x reference)
#include <cuda_runtime.h>
#include <cuda_bf16.h>
#include <math.h>

// Problem constants
#define BB 2
#define SS 2048
#define DD 1024
#define HH 16
#define DKK 64
#define MM (BB * SS)   // 4096 rows for all GEMMs

// ---------------------------------------------------------------------------
// Scratch (device globals; no runtime allocation allowed)
// ---------------------------------------------------------------------------
__device__ float g_Q[BB * HH * SS * DKK];   // [B,H,S,DK]  (tf32-rounded)
__device__ float g_K[BB * HH * SS * DKK];
__device__ float g_V[BB * HH * SS * DKK];
__device__ float g_Ctx[BB * SS * DD];       // [B,S,D]     (tf32-rounded)
__device__ float g_qr[MM * DD];             // tf32-rounded inputs
__device__ float g_kr[MM * DD];
__device__ float g_vr[MM * DD];
__device__ float g_w[4][DD * DD];           // tf32-rounded weights q,k,v,o

// ---------------------------------------------------------------------------
// helpers
// ---------------------------------------------------------------------------
__device__ __forceinline__ unsigned f2tf32(float x) {
    unsigned y;
    asm("cvt.rna.tf32.f32 %0, %1;" : "=r"(y) : "f"(x));
    return y;
}
__device__ __forceinline__ float f2tf32f(float x) { return __uint_as_float(f2tf32(x)); }

__device__ __forceinline__ float ex2(float x) {
    float y;
    asm("ex2.approx.f32 %0, %1;" : "=f"(y) : "f"(x));
    return y;
}

__device__ __forceinline__ void mma_tf32(float* c, const unsigned* a, const unsigned* b) {
    asm volatile("mma.sync.aligned.m16n8k8.row.col.f32.tf32.tf32.f32 "
        "{%0,%1,%2,%3}, {%4,%5,%6,%7}, {%8,%9}, {%0,%1,%2,%3};"
        : "+f"(c[0]), "+f"(c[1]), "+f"(c[2]), "+f"(c[3])
        : "r"(a[0]), "r"(a[1]), "r"(a[2]), "r"(a[3]), "r"(b[0]), "r"(b[1]));
}

__device__ __forceinline__ void cp_async16(void* smem_dst, const void* gmem_src) {
    unsigned s = (unsigned)__cvta_generic_to_shared(smem_dst);
    asm volatile("cp.async.cg.shared.global [%0], [%1], 16;" :: "r"(s), "l"(gmem_src));
}
__device__ __forceinline__ void cp_commit() {
    asm volatile("cp.async.commit_group;");
}
template <int N> __device__ __forceinline__ void cp_wait() {
    asm volatile("cp.async.wait_group %0;" :: "n"(N));
}

// ---------------------------------------------------------------------------
// Prepass: round arrays to tf32 (rna) into scratch. grid.z selects segment.
// ---------------------------------------------------------------------------
struct RoundArgs {
    const float4* src[7];
    float4*       dst[7];
    int           n4[7];
};

__global__ __launch_bounds__(256) void round_tf32_kernel(RoundArgs a)
{
    int z = blockIdx.z;
    const float4* s = a.src[z];
    float4*       d = a.dst[z];
    int n4 = a.n4[z];
    int stride = gridDim.x * blockDim.x;
    for (int i = blockIdx.x * blockDim.x + threadIdx.x; i < n4; i += stride) {
        float4 v = s[i];
        v.x = f2tf32f(v.x); v.y = f2tf32f(v.y);
        v.z = f2tf32f(v.z); v.w = f2tf32f(v.w);
        d[i] = v;
    }
}

// ---------------------------------------------------------------------------
// Pipelined NT GEMM via tf32 tensor cores (operands pre-rounded; no cvt in loop)
//   C[m,n] = sum_k Ain[m,k] * W[n,k] + bias[n]
// BM=BN=128, BK=16, 3-stage cp.async ring, 256 thr (8 warps 2x4, 64x32/warp).
// out_mode: 0 -> C[m*N+n] fp32; 1/2/3 -> scatter tf32-rounded to g_Q/g_K/g_V
// ---------------------------------------------------------------------------
#define RS 20           // smem row stride (floats); frag banks (4g+t) distinct
#define STG 3
#define KT (DD / 16)

struct GemmArgs {
    const float* A[3];
    const float* W[3];
    const float* bias[3];
    float* C;
    int out_mode[3];
};

__global__ __launch_bounds__(256, 2) void gemm_pipe_kernel(GemmArgs args)
{
    __shared__ float As[STG][128 * RS];
    __shared__ float Bs[STG][128 * RS];

    int z = blockIdx.z;
    const float* __restrict__ Ain  = args.A[z];
    const float* __restrict__ W    = args.W[z];
    const float* __restrict__ bias = args.bias[z];
    int out_mode = args.out_mode[z];

    int tid  = threadIdx.x;
    int lane = tid & 31;
    int w    = tid >> 5;
    int wm   = w >> 2;
    int wn   = w & 3;
    int g    = lane >> 2;
    int t    = lane & 3;

    int bm = blockIdx.y * 128;
    int bn = blockIdx.x * 128;

    int r0c = tid >> 1;
    int c0c = (tid & 1) * 8;

    float c[4][4][4];
#pragma unroll
    for (int mi = 0; mi < 4; mi++)
#pragma unroll
        for (int nj = 0; nj < 4; nj++)
#pragma unroll
            for (int e = 0; e < 4; e++) c[mi][nj][e] = 0.0f;

#pragma unroll
    for (int pf = 0; pf < STG - 1; pf++) {
        int k0 = pf * 16;
        cp_async16(&As[pf][r0c * RS + c0c],     &Ain[(size_t)(bm + r0c) * DD + k0 + c0c]);
        cp_async16(&As[pf][r0c * RS + c0c + 4], &Ain[(size_t)(bm + r0c) * DD + k0 + c0c + 4]);
        cp_async16(&Bs[pf][r0c * RS + c0c],     &W[(size_t)(bn + r0c) * DD + k0 + c0c]);
        cp_async16(&Bs[pf][r0c * RS + c0c + 4], &W[(size_t)(bn + r0c) * DD + k0 + c0c + 4]);
        cp_commit();
    }
    cp_wait<STG - 2>();
    __syncthreads();

    for (int kt = 0; kt < KT; kt++) {
        int st = kt % STG;

        if (kt + STG - 1 < KT) {
            int ps = (kt + STG - 1) % STG;
            int k0 = (kt + STG - 1) * 16;
            cp_async16(&As[ps][r0c * RS + c0c],     &Ain[(size_t)(bm + r0c) * DD + k0 + c0c]);
            cp_async16(&As[ps][r0c * RS + c0c + 4], &Ain[(size_t)(bm + r0c) * DD + k0 + c0c + 4]);
            cp_async16(&Bs[ps][r0c * RS + c0c],     &W[(size_t)(bn + r0c) * DD + k0 + c0c]);
            cp_async16(&Bs[ps][r0c * RS + c0c + 4], &W[(size_t)(bn + r0c) * DD + k0 + c0c + 4]);
        }
        cp_commit();

        const float* a_s = As[st];
        const float* b_s = Bs[st];
#pragma unroll
        for (int ks = 0; ks < 2; ks++) {
            unsigned af[4][4], bf[4][2];
#pragma unroll
            for (int mi = 0; mi < 4; mi++) {
                int m = wm * 64 + mi * 16 + g;
                af[mi][0] = __float_as_uint(a_s[m * RS + ks * 8 + t]);
                af[mi][1] = __float_as_uint(a_s[(m + 8) * RS + ks * 8 + t]);
                af[mi][2] = __float_as_uint(a_s[m * RS + ks * 8 + t + 4]);
                af[mi][3] = __float_as_uint(a_s[(m + 8) * RS + ks * 8 + t + 4]);
            }
#pragma unroll
            for (int nj = 0; nj < 4; nj++) {
                int n = wn * 32 + nj * 8 + g;
                bf[nj][0] = __float_as_uint(b_s[n * RS + ks * 8 + t]);
                bf[nj][1] = __float_as_uint(b_s[n * RS + ks * 8 + t + 4]);
            }
#pragma unroll
            for (int mi = 0; mi < 4; mi++)
#pragma unroll
                for (int nj = 0; nj < 4; nj++)
                    mma_tf32(c[mi][nj], af[mi], bf[nj]);
        }

        cp_wait<STG - 2>();
        __syncthreads();
    }

#pragma unroll
    for (int mi = 0; mi < 4; mi++) {
#pragma unroll
        for (int nj = 0; nj < 4; nj++) {
            int m = bm + wm * 64 + mi * 16 + g;
            int n = bn + wn * 32 + nj * 8 + 2 * t;
            float b0 = bias[n], b1 = bias[n + 1];
            if (out_mode == 0) {
                float2 v0 = make_float2(c[mi][nj][0] + b0, c[mi][nj][1] + b1);
                float2 v1 = make_float2(c[mi][nj][2] + b0, c[mi][nj][3] + b1);
                *(float2*)&args.C[(size_t)m * DD + n]       = v0;
                *(float2*)&args.C[(size_t)(m + 8) * DD + n] = v1;
            } else {
                // round to tf32 so attention can consume raw bits
                float2 v0 = make_float2(f2tf32f(c[mi][nj][0] + b0), f2tf32f(c[mi][nj][1] + b1));
                float2 v1 = make_float2(f2tf32f(c[mi][nj][2] + b0), f2tf32f(c[mi][nj][3] + b1));
                int b  = m >> 11;
                int s  = m & (SS - 1);
                int h  = n >> 6;
                int dk = n & (DKK - 1);
                float* dst = (out_mode == 1) ? g_Q : (out_mode == 2) ? g_K : g_V;
                size_t base = (((size_t)(b * HH + h)) * SS) * DKK + dk;
                *(float2*)&dst[base + (size_t)s * DKK]  = v0;
                int s1 = (m + 8) & (SS - 1);
                *(float2*)&dst[base + (size_t)s1 * DKK] = v1;
            }
        }
    }
}

// ---------------------------------------------------------------------------
// Causal flash attention via tf32 tensor cores.
// Q/K/V pre-rounded to tf32 -> no cvt at staging. K/V double-buffered cp.async.
// grid=(S/64, B*H), 128 thr (4 warps); warp owns 16 Q rows. qb reversed so
// heavy CTAs launch first.
// ---------------------------------------------------------------------------
#define SCALE_LOG2E 0.1803368801111244f   // (1/sqrt(64)) * log2(e)

__global__ __launch_bounds__(128) void attn_tc_kernel()
{
    __shared__ unsigned QPs[64][68];      // Q tile then P
    __shared__ float    Ks[2][64][68];    // double-buffered
    __shared__ float    Vs[2][64][72];

    int tid  = threadIdx.x;
    int lane = tid & 31;
    int w    = tid >> 5;
    int g    = lane >> 2;
    int t    = lane & 3;
    int wrow = w * 16;

    int qb = gridDim.x - 1 - blockIdx.x;  // heavy blocks first
    int bh = blockIdx.y;
    int b  = bh >> 4;
    int h  = bh & (HH - 1);
    size_t head = (size_t)bh * SS * DKK;

    // ---- stage Q tile (raw bits; already tf32-rounded) ----
#pragma unroll
    for (int it = 0; it < 8; it++) {
        int i  = it * 128 + tid;
        int r  = i >> 4;
        int c4 = (i & 15) << 2;
        float4 v4 = *(const float4*)&g_Q[head + (size_t)(qb * 64 + r) * DKK + c4];
        QPs[r][c4 + 0] = __float_as_uint(v4.x);
        QPs[r][c4 + 1] = __float_as_uint(v4.y);
        QPs[r][c4 + 2] = __float_as_uint(v4.z);
        QPs[r][c4 + 3] = __float_as_uint(v4.w);
    }

    // ---- prefetch K/V tile 0 into buffer 0 ----
#pragma unroll
    for (int it = 0; it < 8; it++) {
        int ch = it * 128 + tid;          // 0..1023
        int r  = ch >> 4;
        int c4 = (ch & 15) << 2;
        size_t gi = head + (size_t)r * DKK + c4;
        cp_async16(&Ks[0][r][c4], &g_K[gi]);
        cp_async16(&Vs[0][r][c4], &g_V[gi]);
    }
    cp_commit();

    __syncthreads();

    // ---- Q fragments to registers ----
    unsigned qf[8][4];
#pragma unroll
    for (int ks = 0; ks < 8; ks++) {
        qf[ks][0] = QPs[wrow + g][ks * 8 + t];
        qf[ks][1] = QPs[wrow + g + 8][ks * 8 + t];
        qf[ks][2] = QPs[wrow + g][ks * 8 + t + 4];
        qf[ks][3] = QPs[wrow + g + 8][ks * 8 + t + 4];
    }

    float o[8][4];
#pragma unroll
    for (int nj = 0; nj < 8; nj++)
#pragma unroll
        for (int e = 0; e < 4; e++) o[nj][e] = 0.0f;
    float m0 = -1e30f, m1 = -1e30f, l0 = 0.0f, l1 = 0.0f;

    for (int j = 0; j <= qb; j++) {
        int cur = j & 1;
        __syncthreads();   // all warps done reading buffer (j+1)&1 / QPs

        // prefetch tile j+1 into the other buffer
        if (j < qb) {
            int nxt = (j + 1) & 1;
#pragma unroll
            for (int it = 0; it < 8; it++) {
                int ch = it * 128 + tid;
                int r  = ch >> 4;
                int c4 = (ch & 15) << 2;
                size_t gi = head + (size_t)((j + 1) * 64 + r) * DKK + c4;
                cp_async16(&Ks[nxt][r][c4], &g_K[gi]);
                cp_async16(&Vs[nxt][r][c4], &g_V[gi]);
            }
        }
        cp_commit();
        cp_wait<1>();      // tile j resident
        __syncthreads();

        // ---- S = Q @ K^T ----
        float s[8][4];
#pragma unroll
        for (int nj = 0; nj < 8; nj++)
#pragma unroll
            for (int e = 0; e < 4; e++) s[nj][e] = 0.0f;

#pragma unroll
        for (int ks = 0; ks < 8; ks++) {
#pragma unroll
            for (int nj = 0; nj < 8; nj++) {
                unsigned bf[2];
                bf[0] = __float_as_uint(Ks[cur][nj * 8 + g][ks * 8 + t]);
                bf[1] = __float_as_uint(Ks[cur][nj * 8 + g][ks * 8 + t + 4]);
                mma_tf32(s[nj], qf[ks], bf);
            }
        }

#pragma unroll
        for (int nj = 0; nj < 8; nj++)
#pragma unroll
            for (int e = 0; e < 4; e++) s[nj][e] *= SCALE_LOG2E;

        if (j == qb) {  // diagonal tile causal mask
#pragma unroll
            for (int nj = 0; nj < 8; nj++) {
                int c0 = nj * 8 + 2 * t;
                if (c0     > wrow + g)     s[nj][0] = -1e30f;
                if (c0 + 1 > wrow + g)     s[nj][1] = -1e30f;
                if (c0     > wrow + g + 8) s[nj][2] = -1e30f;
                if (c0 + 1 > wrow + g + 8) s[nj][3] = -1e30f;
            }
        }

        float mx0 = -1e30f, mx1 = -1e30f;
#pragma unroll
        for (int nj = 0; nj < 8; nj++) {
            mx0 = fmaxf(mx0, fmaxf(s[nj][0], s[nj][1]));
            mx1 = fmaxf(mx1, fmaxf(s[nj][2], s[nj][3]));
        }
        mx0 = fmaxf(mx0, __shfl_xor_sync(0xffffffffu, mx0, 1));
        mx0 = fmaxf(mx0, __shfl_xor_sync(0xffffffffu, mx0, 2));
        mx1 = fmaxf(mx1, __shfl_xor_sync(0xffffffffu, mx1, 1));
        mx1 = fmaxf(mx1, __shfl_xor_sync(0xffffffffu, mx1, 2));

        float m0n = fmaxf(m0, mx0), m1n = fmaxf(m1, mx1);
        float a0 = ex2(m0 - m0n),   a1 = ex2(m1 - m1n);
        m0 = m0n; m1 = m1n;

        float rs0 = 0.0f, rs1 = 0.0f;
#pragma unroll
        for (int nj = 0; nj < 8; nj++) {
            float p;
            p = ex2(s[nj][0] - m0n); rs0 += p; s[nj][0] = p;
            p = ex2(s[nj][1] - m0n); rs0 += p; s[nj][1] = p;
            p = ex2(s[nj][2] - m1n); rs1 += p; s[nj][2] = p;
            p = ex2(s[nj][3] - m1n); rs1 += p; s[nj][3] = p;
        }
        rs0 += __shfl_xor_sync(0xffffffffu, rs0, 1);
        rs0 += __shfl_xor_sync(0xffffffffu, rs0, 2);
        rs1 += __shfl_xor_sync(0xffffffffu, rs1, 1);
        rs1 += __shfl_xor_sync(0xffffffffu, rs1, 2);

        l0 = l0 * a0 + rs0;
        l1 = l1 * a1 + rs1;
#pragma unroll
        for (int nj = 0; nj < 8; nj++) {
            o[nj][0] *= a0; o[nj][1] *= a0;
            o[nj][2] *= a1; o[nj][3] *= a1;
        }

        // ---- P -> smem (warp-private rows) ----
#pragma unroll
        for (int nj = 0; nj < 8; nj++) {
            int cc = nj * 8 + 2 * t;
            QPs[wrow + g][cc]         = f2tf32(s[nj][0]);
            QPs[wrow + g][cc + 1]     = f2tf32(s[nj][1]);
            QPs[wrow + g + 8][cc]     = f2tf32(s[nj][2]);
            QPs[wrow + g + 8][cc + 1] = f2tf32(s[nj][3]);
        }
        __syncwarp();

        // ---- O += P @ V ----
#pragma unroll
        for (int ks = 0; ks < 8; ks++) {
            unsigned pf[4];
            pf[0] = QPs[wrow + g][ks * 8 + t];
            pf[1] = QPs[wrow + g + 8][ks * 8 + t];
            pf[2] = QPs[wrow + g][ks * 8 + t + 4];
            pf[3] = QPs[wrow + g + 8][ks * 8 + t + 4];
#pragma unroll
            for (int nj = 0; nj < 8; nj++) {
                unsigned vf[2];
                vf[0] = __float_as_uint(Vs[cur][ks * 8 + t][nj * 8 + g]);
                vf[1] = __float_as_uint(Vs[cur][ks * 8 + t + 4][nj * 8 + g]);
                mma_tf32(o[nj], pf, vf);
            }
        }
    }

    // ---- epilogue: normalize, round to tf32 (out-proj consumes raw) ----
    float inv0 = 1.0f / l0, inv1 = 1.0f / l1;
    int row0 = qb * 64 + wrow + g;
    size_t base0 = ((size_t)(b * SS + row0)) * DD + h * 64;
    size_t base1 = base0 + (size_t)8 * DD;
#pragma unroll
    for (int nj = 0; nj < 8; nj++) {
        int cc = nj * 8 + 2 * t;
        *(float2*)&g_Ctx[base0 + cc] =
            make_float2(f2tf32f(o[nj][0] * inv0), f2tf32f(o[nj][1] * inv0));
        *(float2*)&g_Ctx[base1 + cc] =
            make_float2(f2tf32f(o[nj][2] * inv1), f2tf32f(o[nj][3] * inv1));
    }
}

// ---------------------------------------------------------------------------
// kernel_launch
// ---------------------------------------------------------------------------
extern "C" void kernel_launch(void* const* d_in, const int* in_sizes, int n_in,
                              void* d_out, int out_size)
{
    const float* q    = (const float*)d_in[0];
    const float* k    = (const float*)d_in[1];
    const float* v    = (const float*)d_in[2];
    const float* wq_w = (const float*)d_in[4];
    const float* wq_b = (const float*)d_in[5];
    const float* wk_w = (const float*)d_in[6];
    const float* wk_b = (const float*)d_in[7];
    const float* wv_w = (const float*)d_in[8];
    const float* wv_b = (const float*)d_in[9];
    const float* wo_w = (const float*)d_in[10];
    const float* wo_b = (const float*)d_in[11];
    float* out = (float*)d_out;

    void *p_qr, *p_kr, *p_vr, *p_w, *p_ctx;
    cudaGetSymbolAddress(&p_qr, g_qr);
    cudaGetSymbolAddress(&p_kr, g_kr);
    cudaGetSymbolAddress(&p_vr, g_vr);
    cudaGetSymbolAddress(&p_w,  g_w);
    cudaGetSymbolAddress(&p_ctx, g_Ctx);
    float* w0 = (float*)p_w;   // g_w[0]
    float* w1 = w0 + DD * DD;
    float* w2 = w0 + 2 * DD * DD;
    float* w3 = w0 + 3 * DD * DD;

    // ---- prepass: round inputs + weights to tf32 ----
    RoundArgs ra;
    ra.src[0] = (const float4*)q;    ra.dst[0] = (float4*)p_qr; ra.n4[0] = MM * DD / 4;
    ra.src[1] = (const float4*)k;    ra.dst[1] = (float4*)p_kr; ra.n4[1] = MM * DD / 4;
    ra.src[2] = (const float4*)v;    ra.dst[2] = (float4*)p_vr; ra.n4[2] = MM * DD / 4;
    ra.src[3] = (const float4*)wq_w; ra.dst[3] = (float4*)w0;   ra.n4[3] = DD * DD / 4;
    ra.src[4] = (const float4*)wk_w; ra.dst[4] = (float4*)w1;   ra.n4[4] = DD * DD / 4;
    ra.src[5] = (const float4*)wv_w; ra.dst[5] = (float4*)w2;   ra.n4[5] = DD * DD / 4;
    ra.src[6] = (const float4*)wo_w; ra.dst[6] = (float4*)w3;   ra.n4[6] = DD * DD / 4;
    round_tf32_kernel<<<dim3(128, 1, 7), 256>>>(ra);

    // ---- fused QKV projections ----
    GemmArgs qkv;
    qkv.A[0] = (const float*)p_qr; qkv.A[1] = (const float*)p_kr; qkv.A[2] = (const float*)p_vr;
    qkv.W[0] = w0; qkv.W[1] = w1; qkv.W[2] = w2;
    qkv.bias[0] = wq_b; qkv.bias[1] = wk_b; qkv.bias[2] = wv_b;
    qkv.C = nullptr;
    qkv.out_mode[0] = 1; qkv.out_mode[1] = 2; qkv.out_mode[2] = 3;
    gemm_pipe_kernel<<<dim3(DD / 128, MM / 128, 3), 256>>>(qkv);

    // ---- attention ----
    attn_tc_kernel<<<dim3(SS / 64, BB * HH), 128>>>();

    // ---- output projection ----
    GemmArgs og;
    og.A[0] = (const float*)p_ctx; og.A[1] = og.A[0]; og.A[2] = og.A[0];
    og.W[0] = w3; og.W[1] = w3; og.W[2] = w3;
    og.bias[0] = wo_b; og.bias[1] = wo_b; og.bias[2] = wo_b;
    og.C = out;
    og.out_mode[0] = 0; og.out_mode[1] = 0; og.out_mode[2] = 0;
    gemm_pipe_kernel<<<dim3(DD / 128, MM / 128, 1), 256>>>(og);
}